// round 6
// baseline (speedup 1.0000x reference)
#include <cuda_runtime.h>

#define BATCH 32
#define NH    16
#define DK    64
#define DM    1024
#define TC    4096

#define NKV_CTA 32
#define NATTN   (BATCH * NH)

// Scratch (device globals — no allocation allowed)
__device__ float g_qp[BATCH * DM];   // scaled query projection
__device__ float g_kp[BATCH * DM];   // new-token key projection
__device__ float g_vp[BATCH * DM];   // new-token value projection
__device__ float g_x [BATCH * DM];   // attention output (pre out-proj)
__device__ int   g_kv_done;          // zero-init; reset by outproj kernel

// ---------------------------------------------------------------------------
// q-projection: g_qp[b][j] = (q[b]·wq[j] + bq[j]) * 1/sqrt(DK)
// grid (DM/8, 1, 16), block 128: warp computes 2 rows x 2 batches = 4
// interleaved reduce chains; 2048 CTAs / 8192 warps for latency hiding.
// ---------------------------------------------------------------------------
__global__ void qproj_kernel(const float* __restrict__ act,
                             const float* __restrict__ wq,
                             const float* __restrict__ bq)
{
    const int warp = threadIdx.x >> 5;
    const int lane = threadIdx.x & 31;
    const int j0   = (blockIdx.x * 4 + warp) * 2;
    const int b0   = blockIdx.z * 2;

    float4 w[2][8];
#pragma unroll
    for (int r = 0; r < 2; r++) {
        const float* Wr = wq + (size_t)(j0 + r) * DM;
#pragma unroll
        for (int c = 0; c < 8; c++)
            w[r][c] = *(const float4*)(Wr + c * 128 + lane * 4);
    }

    float a[2][2] = {{0.f, 0.f}, {0.f, 0.f}};
#pragma unroll
    for (int c = 0; c < 8; c++) {
#pragma unroll
        for (int bb = 0; bb < 2; bb++) {
            float4 x = *(const float4*)(act + (size_t)(b0 + bb) * DM + c * 128 + lane * 4);
            a[bb][0] += x.x * w[0][c].x + x.y * w[0][c].y + x.z * w[0][c].z + x.w * w[0][c].w;
            a[bb][1] += x.x * w[1][c].x + x.y * w[1][c].y + x.z * w[1][c].z + x.w * w[1][c].w;
        }
    }
#pragma unroll
    for (int off = 16; off; off >>= 1)
#pragma unroll
        for (int bb = 0; bb < 2; bb++) {
            a[bb][0] += __shfl_xor_sync(0xffffffffu, a[bb][0], off);
            a[bb][1] += __shfl_xor_sync(0xffffffffu, a[bb][1], off);
        }
    if (lane == 0) {
        const float bias0 = bq[j0], bias1 = bq[j0 + 1];
#pragma unroll
        for (int bb = 0; bb < 2; bb++) {
            g_qp[(size_t)(b0 + bb) * DM + j0]     = (a[bb][0] + bias0) * 0.125f;
            g_qp[(size_t)(b0 + bb) * DM + j0 + 1] = (a[bb][1] + bias1) * 0.125f;
        }
    }
}

// ---------------------------------------------------------------------------
// Fused kernel, grid = 32 + 512 CTAs x 256 threads:
//   bid 0..31   : k/v-projection producers (write g_kp/g_vp, bump g_kv_done)
//   bid 32..543 : attention consumers, one per (b,h)
// q is already in g_qp (previous kernel). Consumers stream the whole cache,
// then poll g_kv_done (volatile, ~long done by then) before folding in the
// appended token — kv projection cost is fully hidden under the HBM stream.
// ---------------------------------------------------------------------------
__global__ void __launch_bounds__(256)
fused_attn(const float* __restrict__ act,
           const float* __restrict__ Kc, const float* __restrict__ Vc,
           const float* __restrict__ wk, const float* __restrict__ bk,
           const float* __restrict__ wv, const float* __restrict__ bv)
{
    const int cta  = blockIdx.x;
    const int tid  = threadIdx.x;
    const int warp = tid >> 5;
    const int lane = tid & 31;

    if (cta < NKV_CTA) {
        // ============ k/v projection producer ============
        const int gw = cta * 8 + warp;            // 0..255, 8 rows each
        for (int r = 0; r < 8; r++) {
            int ridx = gw * 8 + r;                // 0..2047
            const float* W; const float* bias; float* out;
            if (ridx < 1024) { W = wk; bias = bk; out = g_kp; }
            else { ridx -= 1024; W = wv; bias = bv; out = g_vp; }

            float4 w4[8];
#pragma unroll
            for (int c = 0; c < 8; c++)
                w4[c] = *(const float4*)(W + (size_t)ridx * DM + c * 128 + lane * 4);
            const float bval = bias[ridx];

            for (int p = 0; p < 4; p++) {         // 4 passes x 8 batches
                float acc[8];
#pragma unroll
                for (int i = 0; i < 8; i++) acc[i] = 0.0f;
#pragma unroll
                for (int c = 0; c < 8; c++)
#pragma unroll
                    for (int bb = 0; bb < 8; bb++) {
                        float4 a4 = *(const float4*)(act + (size_t)(p * 8 + bb) * DM
                                                     + c * 128 + lane * 4);
                        acc[bb] += a4.x * w4[c].x + a4.y * w4[c].y
                                 + a4.z * w4[c].z + a4.w * w4[c].w;
                    }
#pragma unroll
                for (int off = 16; off; off >>= 1)
#pragma unroll
                    for (int bb = 0; bb < 8; bb++)
                        acc[bb] += __shfl_xor_sync(0xffffffffu, acc[bb], off);
                if (lane == 0)
#pragma unroll
                    for (int bb = 0; bb < 8; bb++)
                        out[(size_t)(p * 8 + bb) * DM + ridx] = acc[bb] + bval;
            }
        }
        __syncthreads();
        if (tid == 0) {
            __threadfence();
            atomicAdd(&g_kv_done, 1);
        }
        return;
    }

    // ============ attention consumer (R4-proven body) ============
    const int bh   = cta - NKV_CTA;   // 0..511
    const int b    = bh >> 4;
    const int h    = bh & 15;
    const int half = lane >> 4;
    const int li   = lane & 15;

    __shared__ __align__(16) float sqf[DK];
    __shared__ float  sm[16], sl[16];
    __shared__ float4 so[16][16];
    __shared__ float  red2[2];

    if (tid < DK) sqf[tid] = g_qp[b * DM + h * DK + tid];   // pre-scaled
    __syncthreads();

    const float4 q4 = *(const float4*)&sqf[4 * li];

    const float* Kp = Kc + (size_t)bh * TC * DK + half * DK + 4 * li;
    const float* Vp = Vc + (size_t)bh * TC * DK + half * DK + 4 * li;

    float  m = -1e30f;
    float  l = 0.0f;
    float4 o = make_float4(0.f, 0.f, 0.f, 0.f);

    // Block-softmax over 8-key blocks per half (16 keys per warp per iter).
    const int t0 = warp * (TC / 8);
    for (int t = t0; t < t0 + TC / 8; t += 16) {
        float4 kk[8], vv[8];
#pragma unroll
        for (int i = 0; i < 8; i++)
            kk[i] = __ldcs((const float4*)(Kp + (size_t)(t + 2 * i) * DK));
#pragma unroll
        for (int i = 0; i < 8; i++)
            vv[i] = __ldcs((const float4*)(Vp + (size_t)(t + 2 * i) * DK));

        float s[8];
#pragma unroll
        for (int i = 0; i < 8; i++)
            s[i] = kk[i].x * q4.x + kk[i].y * q4.y + kk[i].z * q4.z + kk[i].w * q4.w;
#pragma unroll
        for (int off = 8; off; off >>= 1)
#pragma unroll
            for (int i = 0; i < 8; i++)
                s[i] += __shfl_xor_sync(0xffffffffu, s[i], off);

        float bm01 = fmaxf(s[0], s[1]), bm23 = fmaxf(s[2], s[3]);
        float bm45 = fmaxf(s[4], s[5]), bm67 = fmaxf(s[6], s[7]);
        float bm = fmaxf(fmaxf(bm01, bm23), fmaxf(bm45, bm67));
        float mn = fmaxf(m, bm);

        float p[8];
#pragma unroll
        for (int i = 0; i < 8; i++) p[i] = __expf(s[i] - mn);

        float  lp = 0.0f;
        float4 op = make_float4(0.f, 0.f, 0.f, 0.f);
#pragma unroll
        for (int i = 0; i < 8; i++) {
            lp   += p[i];
            op.x += p[i] * vv[i].x;
            op.y += p[i] * vv[i].y;
            op.z += p[i] * vv[i].z;
            op.w += p[i] * vv[i].w;
        }

        float sc = __expf(m - mn);
        l   = l   * sc + lp;
        o.x = o.x * sc + op.x;
        o.y = o.y * sc + op.y;
        o.z = o.z * sc + op.z;
        o.w = o.w * sc + op.w;
        m   = mn;
    }

    // Publish partial states; wait for kv producers (almost surely done).
    const int idx = warp * 2 + half;
    if (li == 0) { sm[idx] = m; sl[idx] = l; }
    so[idx][li] = o;
    if (tid == 0) {
        while (*(volatile int*)&g_kv_done < NKV_CTA) __nanosleep(200);
        __threadfence();
    }
    __syncthreads();

    // Merge 16 states + appended token. Threads 0..63 own one dim each.
    float prod = 0.0f, M = -1e30f, L = 0.0f, O = 0.0f, vn = 0.0f;
    if (tid < DK) {
        const int d = tid;
        M = sm[0];
#pragma unroll
        for (int i = 1; i < 16; i++) M = fmaxf(M, sm[i]);
#pragma unroll
        for (int i = 0; i < 16; i++) {
            float e = __expf(sm[i] - M);
            L += e * sl[i];
            O += e * ((const float*)so[i])[d];
        }
        float kn = g_kp[b * DM + h * DK + d];
        vn       = g_vp[b * DM + h * DK + d];
        prod = sqf[d] * kn;          // q pre-scaled -> new-token score part
    }
#pragma unroll
    for (int off = 16; off; off >>= 1)
        prod += __shfl_xor_sync(0xffffffffu, prod, off);
    if (lane == 0 && warp < 2) red2[warp] = prod;
    __syncthreads();
    if (tid < DK) {
        float s_new = red2[0] + red2[1];
        float Mf = fmaxf(M, s_new);
        float ef = __expf(M - Mf);
        float pn = __expf(s_new - Mf);
        float Lf = L * ef + pn;
        float Of = O * ef + pn * vn;
        g_x[b * DM + h * DK + tid] = Of / Lf;
    }
}

// ---------------------------------------------------------------------------
// Output projection: out[b][j] = g_x[b]·wo[j] + bo[j].
// grid (DM/8, 1, 16), block 128 (2 batches/CTA -> 8192 warps). Also resets
// the producer counter for the next graph replay.
// ---------------------------------------------------------------------------
__global__ void outproj_kernel(const float* __restrict__ wo,
                               const float* __restrict__ bo,
                               float* __restrict__ out)
{
    if (blockIdx.x == 0 && blockIdx.z == 0 && threadIdx.x == 0)
        g_kv_done = 0;

    const int warp = threadIdx.x >> 5;
    const int lane = threadIdx.x & 31;
    const int j0   = (blockIdx.x * 4 + warp) * 2;
    const int b0   = blockIdx.z * 2;

    float4 w[2][8];
#pragma unroll
    for (int r = 0; r < 2; r++) {
        const float* Wr = wo + (size_t)(j0 + r) * DM;
#pragma unroll
        for (int c = 0; c < 8; c++)
            w[r][c] = *(const float4*)(Wr + c * 128 + lane * 4);
    }

    float a[2][2] = {{0.f, 0.f}, {0.f, 0.f}};
#pragma unroll
    for (int c = 0; c < 8; c++) {
#pragma unroll
        for (int bb = 0; bb < 2; bb++) {
            float4 x = *(const float4*)(g_x + (size_t)(b0 + bb) * DM + c * 128 + lane * 4);
            a[bb][0] += x.x * w[0][c].x + x.y * w[0][c].y + x.z * w[0][c].z + x.w * w[0][c].w;
            a[bb][1] += x.x * w[1][c].x + x.y * w[1][c].y + x.z * w[1][c].z + x.w * w[1][c].w;
        }
    }
#pragma unroll
    for (int off = 16; off; off >>= 1)
#pragma unroll
        for (int bb = 0; bb < 2; bb++) {
            a[bb][0] += __shfl_xor_sync(0xffffffffu, a[bb][0], off);
            a[bb][1] += __shfl_xor_sync(0xffffffffu, a[bb][1], off);
        }
    if (lane == 0) {
        const float bias0 = bo[j0], bias1 = bo[j0 + 1];
#pragma unroll
        for (int bb = 0; bb < 2; bb++) {
            out[(size_t)(b0 + bb) * DM + j0]     = a[bb][0] + bias0;
            out[(size_t)(b0 + bb) * DM + j0 + 1] = a[bb][1] + bias1;
        }
    }
}

// ---------------------------------------------------------------------------
// inputs (metadata order): 0 q, 1 key_pre, 2 value_pre,
//   3 wq, 4 bq, 5 wk, 6 bk, 7 wv, 8 bv, 9 wo, 10 bo
// output: [32, 1, 1024] fp32
// ---------------------------------------------------------------------------
extern "C" void kernel_launch(void* const* d_in, const int* in_sizes, int n_in,
                              void* d_out, int out_size)
{
    const float* q   = (const float*)d_in[0];
    const float* Kc  = (const float*)d_in[1];
    const float* Vc  = (const float*)d_in[2];
    const float* wq  = (const float*)d_in[3];
    const float* bq  = (const float*)d_in[4];
    const float* wk  = (const float*)d_in[5];
    const float* bk  = (const float*)d_in[6];
    const float* wv  = (const float*)d_in[7];
    const float* bv  = (const float*)d_in[8];
    const float* wo  = (const float*)d_in[9];
    const float* bo  = (const float*)d_in[10];
    float* out = (float*)d_out;

    qproj_kernel<<<dim3(DM / 8, 1, 16), 128>>>(q, wq, bq);
    fused_attn<<<NKV_CTA + NATTN, 256>>>(q, Kc, Vc, wk, bk, wv, bv);
    outproj_kernel<<<dim3(DM / 8, 1, 16), 128>>>(wo, bo, out);
}

// round 7
// speedup vs baseline: 1.5068x; 1.5068x over previous
#include <cuda_runtime.h>

#define BATCH 32
#define NH    16
#define DK    64
#define DM    1024
#define TC    4096

// Scratch (device globals — no allocation allowed in kernel_launch)
__device__ float g_qp[BATCH * DM];   // scaled query projection
__device__ float g_kp[BATCH * DM];   // new-token key projection
__device__ float g_vp[BATCH * DM];   // new-token value projection
__device__ float g_x [BATCH * DM];   // attention output (pre out-proj)

// ---------------------------------------------------------------------------
// GEMV projection (R4-proven): out[b][j] = (act[b]·W[j] + bias[j]) * scale
// mode 0: QKV — grid.y selects {wq->g_qp(*qscale), wk->g_kp, wv->g_vp}
// mode 1: out-projection — act = g_x (device symbol), W0/B0 -> out_ext
// grid = (DM/8, nmat, 8): 4 batches/CTA, 8 interleaved reduce chains.
// ---------------------------------------------------------------------------
__global__ void proj_kernel(int mode,
                            const float* __restrict__ act_ext,
                            const float* __restrict__ W0, const float* __restrict__ B0,
                            const float* __restrict__ W1, const float* __restrict__ B1,
                            const float* __restrict__ W2, const float* __restrict__ B2,
                            float* __restrict__ out_ext,
                            float qscale)
{
    const float* act;
    const float* W;
    const float* bias;
    float* out;
    float scale = 1.0f;

    if (mode == 1) {
        act = g_x;  W = W0; bias = B0; out = out_ext;
    } else {
        act = act_ext;
        if (blockIdx.y == 0)      { W = W0; bias = B0; out = g_qp; scale = qscale; }
        else if (blockIdx.y == 1) { W = W1; bias = B1; out = g_kp; }
        else                      { W = W2; bias = B2; out = g_vp; }
    }

    const int warp = threadIdx.x >> 5;
    const int lane = threadIdx.x & 31;
    const int j0   = (blockIdx.x * 4 + warp) * 2;   // 2 rows per warp
    const int b0   = blockIdx.z * 4;                // 4 batches per z-slice

    float4 w[2][8];
#pragma unroll
    for (int r = 0; r < 2; r++) {
        const float* Wr = W + (size_t)(j0 + r) * DM;
#pragma unroll
        for (int c = 0; c < 8; c++)
            w[r][c] = *(const float4*)(Wr + c * 128 + lane * 4);
    }

    float a[4][2];
#pragma unroll
    for (int b = 0; b < 4; b++) { a[b][0] = 0.0f; a[b][1] = 0.0f; }

#pragma unroll
    for (int c = 0; c < 8; c++) {
#pragma unroll
        for (int b = 0; b < 4; b++) {
            float4 x = *(const float4*)(act + (size_t)(b0 + b) * DM + c * 128 + lane * 4);
            a[b][0] += x.x * w[0][c].x + x.y * w[0][c].y + x.z * w[0][c].z + x.w * w[0][c].w;
            a[b][1] += x.x * w[1][c].x + x.y * w[1][c].y + x.z * w[1][c].z + x.w * w[1][c].w;
        }
    }

#pragma unroll
    for (int off = 16; off; off >>= 1) {
#pragma unroll
        for (int b = 0; b < 4; b++) {
            a[b][0] += __shfl_xor_sync(0xffffffffu, a[b][0], off);
            a[b][1] += __shfl_xor_sync(0xffffffffu, a[b][1], off);
        }
    }

    if (lane == 0) {
        const float bias0 = bias[j0], bias1 = bias[j0 + 1];
#pragma unroll
        for (int b = 0; b < 4; b++) {
            out[(size_t)(b0 + b) * DM + j0]     = (a[b][0] + bias0) * scale;
            out[(size_t)(b0 + b) * DM + j0 + 1] = (a[b][1] + bias1) * scale;
        }
    }
}

// ---------------------------------------------------------------------------
// Flash-decode attention over 4096 cached keys + 1 new token.
// One CTA per (b,h): 512 CTAs x 256 threads (8 warps).
// __launch_bounds__(256, 4): <=64 regs -> 4 CTAs/SM -> ALL 512 CTAs resident
// in ONE wave (148*4=592 slots), 32 warps/SM for latency hiding, no wave-2
// tail. This is the change vs R4 (which ran 2 waves at ~100 regs).
//
// float4 / half-warp layout: 16 lanes cover DK=64; block-softmax over 4-key
// blocks per half (8 keys / 8 LDG.128 in flight per warp per iter):
// 4 independent shfl chains -> block max -> 4 parallel exps -> one rescale.
// K/V via __ldcs (streaming, zero reuse).
// ---------------------------------------------------------------------------
__global__ void __launch_bounds__(256, 4)
attn_kernel(const float* __restrict__ Kc,
            const float* __restrict__ Vc)
{
    const int bh   = blockIdx.x;       // 0..511
    const int b    = bh >> 4;
    const int h    = bh & 15;
    const int warp = threadIdx.x >> 5;
    const int lane = threadIdx.x & 31;
    const int half = lane >> 4;        // 0 or 1
    const int li   = lane & 15;        // lane within half; dims 4*li..4*li+3

    __shared__ float4 sq[16];          // q, pre-scaled by 1/sqrt(DK)
    __shared__ float  sm[16], sl[16];
    __shared__ float4 so[16][16];

    if (threadIdx.x < 16)
        sq[threadIdx.x] = *(const float4*)(g_qp + b * DM + h * DK + 4 * threadIdx.x);
    __syncthreads();

    const float4 q4 = sq[li];

    const float* Kp = Kc + (size_t)bh * TC * DK + (size_t)half * DK + 4 * li;
    const float* Vp = Vc + (size_t)bh * TC * DK + (size_t)half * DK + 4 * li;

    float  m = -1e30f;
    float  l = 0.0f;
    float4 o = make_float4(0.f, 0.f, 0.f, 0.f);

    const int t0 = warp * (TC / 8);    // 512 keys per warp; 4/half per iter
    for (int t = t0; t < t0 + TC / 8; t += 8) {
        float4 kk[4], vv[4];
#pragma unroll
        for (int i = 0; i < 4; i++)
            kk[i] = __ldcs((const float4*)(Kp + (size_t)(t + 2 * i) * DK));
#pragma unroll
        for (int i = 0; i < 4; i++)
            vv[i] = __ldcs((const float4*)(Vp + (size_t)(t + 2 * i) * DK));

        float s[4];
#pragma unroll
        for (int i = 0; i < 4; i++)
            s[i] = kk[i].x * q4.x + kk[i].y * q4.y + kk[i].z * q4.z + kk[i].w * q4.w;
#pragma unroll
        for (int off = 8; off; off >>= 1)
#pragma unroll
            for (int i = 0; i < 4; i++)
                s[i] += __shfl_xor_sync(0xffffffffu, s[i], off);   // within half

        float bm = fmaxf(fmaxf(s[0], s[1]), fmaxf(s[2], s[3]));
        float mn = fmaxf(m, bm);

        float p[4];
#pragma unroll
        for (int i = 0; i < 4; i++) p[i] = __expf(s[i] - mn);

        float  lp = 0.0f;
        float4 op = make_float4(0.f, 0.f, 0.f, 0.f);
#pragma unroll
        for (int i = 0; i < 4; i++) {
            lp   += p[i];
            op.x += p[i] * vv[i].x;
            op.y += p[i] * vv[i].y;
            op.z += p[i] * vv[i].z;
            op.w += p[i] * vv[i].w;
        }

        float sc = __expf(m - mn);
        l   = l   * sc + lp;
        o.x = o.x * sc + op.x;
        o.y = o.y * sc + op.y;
        o.z = o.z * sc + op.z;
        o.w = o.w * sc + op.w;
        m   = mn;
    }

    // New (appended) token: warp 0 computes the score; half 0 folds it in.
    if (warp == 0) {
        float4 kk = *(const float4*)(g_kp + b * DM + h * DK + 4 * li);
        float4 vv = *(const float4*)(g_vp + b * DM + h * DK + 4 * li);
        float s = kk.x * q4.x + kk.y * q4.y + kk.z * q4.z + kk.w * q4.w;
#pragma unroll
        for (int off = 8; off; off >>= 1)
            s += __shfl_xor_sync(0xffffffffu, s, off);
        if (half == 0) {
            float mn = fmaxf(m, s);
            float sc = __expf(m - mn);
            float p  = __expf(s - mn);
            l   = l   * sc + p;
            o.x = o.x * sc + p * vv.x;
            o.y = o.y * sc + p * vv.y;
            o.z = o.z * sc + p * vv.z;
            o.w = o.w * sc + p * vv.w;
            m   = mn;
        }
    }

    const int idx = warp * 2 + half;   // 16 partial states
    if (li == 0) { sm[idx] = m; sl[idx] = l; }
    so[idx][li] = o;
    __syncthreads();

    // Combine 16 partial states; threads 0..63 each own one output dim.
    if (threadIdx.x < DK) {
        const int d = threadIdx.x;
        float M = sm[0];
#pragma unroll
        for (int i = 1; i < 16; i++) M = fmaxf(M, sm[i]);
        float L = 0.0f, O = 0.0f;
#pragma unroll
        for (int i = 0; i < 16; i++) {
            float e = __expf(sm[i] - M);
            L += e * sl[i];
            O += e * ((const float*)so[i])[d];
        }
        g_x[b * DM + h * DK + d] = O / L;
    }
}

// ---------------------------------------------------------------------------
// inputs (metadata order): 0 q, 1 key_pre, 2 value_pre,
//   3 wq, 4 bq, 5 wk, 6 bk, 7 wv, 8 bv, 9 wo, 10 bo
// output: [32, 1, 1024] fp32
// ---------------------------------------------------------------------------
extern "C" void kernel_launch(void* const* d_in, const int* in_sizes, int n_in,
                              void* d_out, int out_size)
{
    const float* q   = (const float*)d_in[0];
    const float* Kc  = (const float*)d_in[1];
    const float* Vc  = (const float*)d_in[2];
    const float* wq  = (const float*)d_in[3];
    const float* bq  = (const float*)d_in[4];
    const float* wk  = (const float*)d_in[5];
    const float* bk  = (const float*)d_in[6];
    const float* wv  = (const float*)d_in[7];
    const float* bv  = (const float*)d_in[8];
    const float* wo  = (const float*)d_in[9];
    const float* bo  = (const float*)d_in[10];
    float* out = (float*)d_out;

    const float qscale = 0.125f;  // 1/sqrt(DK)

    // QKV projections (grid.y selects matrix; q gets the softmax scale folded in)
    proj_kernel<<<dim3(DM / 8, 3, 8), 128>>>(0, q, wq, bq, wk, bk, wv, bv,
                                             nullptr, qscale);

    // Flash-decode attention over the cache + appended token (single wave)
    attn_kernel<<<BATCH * NH, 256>>>(Kc, Vc);

    // Output projection: reads g_x via device-side symbol, writes d_out
    proj_kernel<<<dim3(DM / 8, 1, 8), 128>>>(1, nullptr, wo, bo, nullptr, nullptr,
                                             nullptr, nullptr, out, 1.0f);
}